// round 7
// baseline (speedup 1.0000x reference)
#include <cuda_runtime.h>
#include <cstdint>

typedef unsigned long long ull;

#define T_STEPS 8
#define NN 20000
#define EE 320000
#define ET (EE + NN)

// ---------------- scratch (static device globals; no allocation at run time) ------------
__device__ __align__(16) float g_h1lin[NN * 256];
__device__ __align__(16) float g_als1[NN * 4];
__device__ __align__(16) float g_ald1[NN * 4];
__device__ __align__(16) float g_ex1[ET * 4];
__device__ __align__(16) float g_sum1[NN * 4];
__device__ __align__(16) float g_out1[NN * 256];
__device__ __align__(16) float g_h2lin[NN * 64];
__device__ __align__(16) float g_als2[NN];
__device__ __align__(16) float g_ald2[NN];
__device__ __align__(16) float g_ex2[ET];
__device__ __align__(16) float g_sum2[NN];
__device__ __align__(16) float g_h2[NN * 64];
__device__ __align__(16) float g_P[NN * 384];
__device__ __align__(16) float g_Q[NN * 384];
__device__ __align__(16) float g_gi[(size_t)EE * 384];
__device__ __align__(16) float g_gh[(size_t)EE * 384];
__device__ __align__(16) float g_h0[(size_t)EE * 128];
__device__ __align__(16) float g_h1s[(size_t)EE * 128];
__device__ __align__(16) float g_dec1[(size_t)EE * 64];

// ---------------- packed fp32x2 helpers (sm_103a FFMA2) ------------
__device__ __forceinline__ ull dup2(float x) {
    ull r;
    unsigned u = __float_as_uint(x);
    asm("mov.b64 %0, {%1, %1};" : "=l"(r) : "r"(u));
    return r;
}
__device__ __forceinline__ ull ffma2(ull a, ull b, ull c) {
    ull d;
    asm("fma.rn.f32x2 %0, %1, %2, %3;" : "=l"(d) : "l"(a), "l"(b), "l"(c));
    return d;
}

// ---------------- GEMM: C[M,Ntot] = A[M,K] * B (+bias) ------------
// B_NK = true : B is [Ntot, K] row-major with row stride ldb   (C = A * B^T)
// B_NK = false: B is [K, Ntot] row-major with row stride ldb   (C = A * B)
// Tile 128x64, BK=16, 256 threads, 8x4 per thread, FFMA2 pairs along M.
template <bool B_NK, bool RELU>
__global__ void __launch_bounds__(256) sgemm_kernel(
    const float* __restrict__ A, const float* __restrict__ B,
    const float* __restrict__ bias, float* __restrict__ C,
    int M, int K, int ldb, int ldc)
{
    __shared__ float As[16][128];
    __shared__ float Bs[16][64];
    const int tid = threadIdx.x;
    const int m0 = blockIdx.x * 128;
    const int n0 = blockIdx.y * 64;
    const int tx = tid & 15;   // n direction
    const int ty = tid >> 4;   // m direction

    ull acc[4][4];
#pragma unroll
    for (int i = 0; i < 4; i++)
#pragma unroll
        for (int j = 0; j < 4; j++) acc[i][j] = 0ULL;

    const int ar = tid >> 2;          // 0..63
    const int ac = (tid & 3) << 2;    // 0,4,8,12
    const int nIter = K >> 4;         // K % 16 == 0 by construction

    for (int it = 0; it < nIter; ++it) {
        const int k0 = it << 4;
        // load A tile (transposed into smem), guard M
#pragma unroll
        for (int half = 0; half < 2; ++half) {
            int row = ar + half * 64;
            float4 v = make_float4(0.f, 0.f, 0.f, 0.f);
            if (m0 + row < M)
                v = *reinterpret_cast<const float4*>(A + (size_t)(m0 + row) * K + k0 + ac);
            As[ac + 0][row] = v.x; As[ac + 1][row] = v.y;
            As[ac + 2][row] = v.z; As[ac + 3][row] = v.w;
        }
        // load B tile
        if (B_NK) {
            int n = tid >> 2;  // 0..63
            float4 v = *reinterpret_cast<const float4*>(B + (size_t)(n0 + n) * ldb + k0 + ac);
            Bs[ac + 0][n] = v.x; Bs[ac + 1][n] = v.y;
            Bs[ac + 2][n] = v.z; Bs[ac + 3][n] = v.w;
        } else {
            int kk = tid >> 4;          // 0..15
            int nn = (tid & 15) << 2;   // 0..60
            *reinterpret_cast<float4*>(&Bs[kk][nn]) =
                *reinterpret_cast<const float4*>(B + (size_t)(k0 + kk) * ldb + n0 + nn);
        }
        __syncthreads();
#pragma unroll
        for (int kk = 0; kk < 16; ++kk) {
            ulonglong2 aA = *reinterpret_cast<const ulonglong2*>(&As[kk][ty * 8]);
            ulonglong2 aB = *reinterpret_cast<const ulonglong2*>(&As[kk][ty * 8 + 4]);
            float4 b = *reinterpret_cast<const float4*>(&Bs[kk][tx * 4]);
            ull am0 = aA.x, am1 = aA.y, am2 = aB.x, am3 = aB.y;
            ull bb0 = dup2(b.x), bb1 = dup2(b.y), bb2 = dup2(b.z), bb3 = dup2(b.w);
            acc[0][0] = ffma2(am0, bb0, acc[0][0]); acc[0][1] = ffma2(am0, bb1, acc[0][1]);
            acc[0][2] = ffma2(am0, bb2, acc[0][2]); acc[0][3] = ffma2(am0, bb3, acc[0][3]);
            acc[1][0] = ffma2(am1, bb0, acc[1][0]); acc[1][1] = ffma2(am1, bb1, acc[1][1]);
            acc[1][2] = ffma2(am1, bb2, acc[1][2]); acc[1][3] = ffma2(am1, bb3, acc[1][3]);
            acc[2][0] = ffma2(am2, bb0, acc[2][0]); acc[2][1] = ffma2(am2, bb1, acc[2][1]);
            acc[2][2] = ffma2(am2, bb2, acc[2][2]); acc[2][3] = ffma2(am2, bb3, acc[2][3]);
            acc[3][0] = ffma2(am3, bb0, acc[3][0]); acc[3][1] = ffma2(am3, bb1, acc[3][1]);
            acc[3][2] = ffma2(am3, bb2, acc[3][2]); acc[3][3] = ffma2(am3, bb3, acc[3][3]);
        }
        __syncthreads();
    }

    float4 bv = make_float4(0.f, 0.f, 0.f, 0.f);
    if (bias) bv = *reinterpret_cast<const float4*>(bias + n0 + tx * 4);
#pragma unroll
    for (int i = 0; i < 4; i++) {
        float lo[4], hi[4];
#pragma unroll
        for (int j = 0; j < 4; j++) {
            lo[j] = __uint_as_float((unsigned)(acc[i][j] & 0xffffffffULL));
            hi[j] = __uint_as_float((unsigned)(acc[i][j] >> 32));
        }
        float4 ce = make_float4(lo[0] + bv.x, lo[1] + bv.y, lo[2] + bv.z, lo[3] + bv.w);
        float4 co = make_float4(hi[0] + bv.x, hi[1] + bv.y, hi[2] + bv.z, hi[3] + bv.w);
        if (RELU) {
            ce.x = fmaxf(ce.x, 0.f); ce.y = fmaxf(ce.y, 0.f);
            ce.z = fmaxf(ce.z, 0.f); ce.w = fmaxf(ce.w, 0.f);
            co.x = fmaxf(co.x, 0.f); co.y = fmaxf(co.y, 0.f);
            co.z = fmaxf(co.z, 0.f); co.w = fmaxf(co.w, 0.f);
        }
        int m = m0 + ty * 8 + i * 2;
        if (m < M)
            *reinterpret_cast<float4*>(C + (size_t)m * ldc + n0 + tx * 4) = ce;
        if (m + 1 < M)
            *reinterpret_cast<float4*>(C + (size_t)(m + 1) * ldc + n0 + tx * 4) = co;
    }
}

// ---------------- GAT attention logits ------------
__global__ void alpha4_kernel(const float* __restrict__ h, const float* __restrict__ av,
                              const float* __restrict__ dv, float* __restrict__ als,
                              float* __restrict__ ald)
{
    int idx = blockIdx.x * blockDim.x + threadIdx.x;
    if (idx >= NN * 4) return;
    int i = idx >> 2, hh = idx & 3;
    const float* hp = h + (size_t)i * 256 + hh * 64;
    const float* ap = av + hh * 64;
    const float* dp = dv + hh * 64;
    float ss = 0.f, sd = 0.f;
#pragma unroll
    for (int c = 0; c < 64; c++) { float v = hp[c]; ss += v * ap[c]; sd += v * dp[c]; }
    als[idx] = ss; ald[idx] = sd;
}

__global__ void alpha1_kernel(const float* __restrict__ h, const float* __restrict__ av,
                              const float* __restrict__ dv, float* __restrict__ als,
                              float* __restrict__ ald)
{
    int i = blockIdx.x * blockDim.x + threadIdx.x;
    if (i >= NN) return;
    const float* hp = h + (size_t)i * 64;
    float ss = 0.f, sd = 0.f;
#pragma unroll
    for (int c = 0; c < 64; c++) { float v = hp[c]; ss += v * av[c]; sd += v * dv[c]; }
    als[i] = ss; ald[i] = sd;
}

// ---------------- edge softmax numerator + denominator (max-shift skipped: exact softmax) --
template <int H>
__global__ void edge_exp_kernel(const int* __restrict__ ei, const float* __restrict__ als,
                                const float* __restrict__ ald, float* __restrict__ exbuf,
                                float* __restrict__ sums)
{
    int idx = blockIdx.x * blockDim.x + threadIdx.x;
    if (idx >= ET * H) return;
    int k = idx / H, hh = idx % H;
    int s, d;
    if (k < EE) { s = ei[k]; d = ei[EE + k]; } else { s = k - EE; d = s; }
    float e = als[s * H + hh] + ald[d * H + hh];
    e = (e >= 0.f) ? e : 0.2f * e;      // leaky_relu(0.2)
    float ex = expf(e);
    exbuf[(size_t)k * H + hh] = ex;
    atomicAdd(&sums[d * H + hh], ex);
}

// ---------------- weighted scatter aggregation ------------
template <int HC, int C>
__global__ void edge_agg_kernel(const int* __restrict__ ei, const float* __restrict__ hlin,
                                const float* __restrict__ exbuf, const float* __restrict__ sums,
                                float* __restrict__ outp)
{
    int idx = blockIdx.x * blockDim.x + threadIdx.x;
    if (idx >= ET * HC) return;
    int k = idx / HC, r = idx % HC;
    constexpr int H = HC / C;
    int hh = r / C;
    int s, d;
    if (k < EE) { s = ei[k]; d = ei[EE + k]; } else { s = k - EE; d = s; }
    float att = exbuf[(size_t)k * H + hh] / (sums[d * H + hh] + 1e-16f);
    atomicAdd(&outp[(size_t)d * HC + r], hlin[(size_t)s * HC + r] * att);
}

// ---------------- pointwise ------------
__global__ void elu_bias_kernel(float* __restrict__ x, const float* __restrict__ b, int total, int C)
{
    int i = blockIdx.x * blockDim.x + threadIdx.x;
    if (i >= total) return;
    float v = x[i] + b[i % C];
    x[i] = (v > 0.f) ? v : expm1f(v);
}
__global__ void bias_kernel(float* __restrict__ x, const float* __restrict__ b, int total, int C)
{
    int i = blockIdx.x * blockDim.x + threadIdx.x;
    if (i >= total) return;
    x[i] += b[i % C];
}

// ---------------- GRU gates ------------
// layer 0: gi gathered as P[src] + Q[dst] (node-level factorization of emb @ Wih0^T)
__global__ void gru_gate0_kernel(const int* __restrict__ ei, const float* __restrict__ P,
                                 const float* __restrict__ Q, const float* __restrict__ gh,
                                 float* __restrict__ h)
{
    int idx = blockIdx.x * blockDim.x + threadIdx.x;
    if (idx >= EE * 128) return;
    int e = idx >> 7, j = idx & 127;
    int s = ei[e], d = ei[EE + e];
    const float* Ps = P + (size_t)s * 384;
    const float* Qd = Q + (size_t)d * 384;
    const float* g = gh + (size_t)e * 384;
    float ir = Ps[j] + Qd[j];
    float iz = Ps[128 + j] + Qd[128 + j];
    float in_ = Ps[256 + j] + Qd[256 + j];
    float hr = g[j], hz = g[128 + j], hn = g[256 + j];
    float r = 1.f / (1.f + expf(-(ir + hr)));
    float z = 1.f / (1.f + expf(-(iz + hz)));
    float n = tanhf(in_ + r * hn);
    float hp = h[idx];
    h[idx] = (1.f - z) * n + z * hp;
}

__global__ void gru_gate_kernel(const float* __restrict__ gi, const float* __restrict__ gh,
                                float* __restrict__ h)
{
    int idx = blockIdx.x * blockDim.x + threadIdx.x;
    if (idx >= EE * 128) return;
    int e = idx >> 7, j = idx & 127;
    const float* gip = gi + (size_t)e * 384;
    const float* ghp = gh + (size_t)e * 384;
    float r = 1.f / (1.f + expf(-(gip[j] + ghp[j])));
    float z = 1.f / (1.f + expf(-(gip[128 + j] + ghp[128 + j])));
    float n = tanhf(gip[256 + j] + r * ghp[256 + j]);
    float hp = h[idx];
    h[idx] = (1.f - z) * n + z * hp;
}

// ---------------- decoder stage 2 (GEMV N=1) ------------
__global__ void decoder2_kernel(const float* __restrict__ d1, const float* __restrict__ Wd2,
                                const float* __restrict__ bd2, float* __restrict__ out)
{
    int e = blockIdx.x * blockDim.x + threadIdx.x;
    if (e >= EE) return;
    const float* r = d1 + (size_t)e * 64;
    float s = 0.f;
#pragma unroll
    for (int c = 0; c < 64; c++) s += r[c] * Wd2[c];
    out[e] = s + bd2[0];
}

// ---------------- host orchestration ------------
static inline dim3 ggrid(int M, int Ntot) { return dim3((M + 127) / 128, Ntot / 64); }
static inline int gb(int n) { return (n + 255) / 256; }

extern "C" void kernel_launch(void* const* d_in, const int* in_sizes, int n_in,
                              void* d_out, int out_size)
{
    (void)in_sizes; (void)n_in; (void)out_size;
    const float* x_seq  = (const float*)d_in[0];
    const int*   ei     = (const int*)d_in[1];
    const float* W1     = (const float*)d_in[2];
    const float* a_src1 = (const float*)d_in[3];
    const float* a_dst1 = (const float*)d_in[4];
    const float* b1     = (const float*)d_in[5];
    const float* W2     = (const float*)d_in[6];
    const float* a_src2 = (const float*)d_in[7];
    const float* a_dst2 = (const float*)d_in[8];
    const float* b2     = (const float*)d_in[9];
    const float* Wih0   = (const float*)d_in[10];
    const float* Whh0   = (const float*)d_in[11];
    const float* bih0   = (const float*)d_in[12];
    const float* bhh0   = (const float*)d_in[13];
    const float* Wih1   = (const float*)d_in[14];
    const float* Whh1   = (const float*)d_in[15];
    const float* bih1   = (const float*)d_in[16];
    const float* bhh1   = (const float*)d_in[17];
    const float* Wd1    = (const float*)d_in[18];
    const float* bd1    = (const float*)d_in[19];
    const float* Wd2    = (const float*)d_in[20];
    const float* bd2    = (const float*)d_in[21];
    float* out = (float*)d_out;

    float *p_h1lin, *p_als1, *p_ald1, *p_ex1, *p_sum1, *p_out1;
    float *p_h2lin, *p_als2, *p_ald2, *p_ex2, *p_sum2, *p_h2;
    float *p_P, *p_Q, *p_gi, *p_gh, *p_h0, *p_h1s, *p_dec1;
    cudaGetSymbolAddress((void**)&p_h1lin, g_h1lin);
    cudaGetSymbolAddress((void**)&p_als1, g_als1);
    cudaGetSymbolAddress((void**)&p_ald1, g_ald1);
    cudaGetSymbolAddress((void**)&p_ex1, g_ex1);
    cudaGetSymbolAddress((void**)&p_sum1, g_sum1);
    cudaGetSymbolAddress((void**)&p_out1, g_out1);
    cudaGetSymbolAddress((void**)&p_h2lin, g_h2lin);
    cudaGetSymbolAddress((void**)&p_als2, g_als2);
    cudaGetSymbolAddress((void**)&p_ald2, g_ald2);
    cudaGetSymbolAddress((void**)&p_ex2, g_ex2);
    cudaGetSymbolAddress((void**)&p_sum2, g_sum2);
    cudaGetSymbolAddress((void**)&p_h2, g_h2);
    cudaGetSymbolAddress((void**)&p_P, g_P);
    cudaGetSymbolAddress((void**)&p_Q, g_Q);
    cudaGetSymbolAddress((void**)&p_gi, g_gi);
    cudaGetSymbolAddress((void**)&p_gh, g_gh);
    cudaGetSymbolAddress((void**)&p_h0, g_h0);
    cudaGetSymbolAddress((void**)&p_h1s, g_h1s);
    cudaGetSymbolAddress((void**)&p_dec1, g_dec1);

    // reset recurrent state every call (graph replays must be identical)
    cudaMemsetAsync(p_h0, 0, (size_t)EE * 128 * sizeof(float), 0);
    cudaMemsetAsync(p_h1s, 0, (size_t)EE * 128 * sizeof(float), 0);

    for (int t = 0; t < T_STEPS; ++t) {
        const float* x_t = x_seq + (size_t)t * NN * 32;

        // ---- GAT layer 1 ----
        cudaMemsetAsync(p_out1, 0, (size_t)NN * 256 * sizeof(float), 0);
        cudaMemsetAsync(p_sum1, 0, (size_t)NN * 4 * sizeof(float), 0);
        sgemm_kernel<false, false><<<ggrid(NN, 256), 256>>>(x_t, W1, nullptr, p_h1lin,
                                                            NN, 32, 256, 256);
        alpha4_kernel<<<gb(NN * 4), 256>>>(p_h1lin, a_src1, a_dst1, p_als1, p_ald1);
        edge_exp_kernel<4><<<gb(ET * 4), 256>>>(ei, p_als1, p_ald1, p_ex1, p_sum1);
        edge_agg_kernel<256, 64><<<gb(ET * 256), 256>>>(ei, p_h1lin, p_ex1, p_sum1, p_out1);
        elu_bias_kernel<<<gb(NN * 256), 256>>>(p_out1, b1, NN * 256, 256);

        // ---- GAT layer 2 ----
        cudaMemsetAsync(p_h2, 0, (size_t)NN * 64 * sizeof(float), 0);
        cudaMemsetAsync(p_sum2, 0, (size_t)NN * sizeof(float), 0);
        sgemm_kernel<false, false><<<ggrid(NN, 64), 256>>>(p_out1, W2, nullptr, p_h2lin,
                                                           NN, 256, 64, 64);
        alpha1_kernel<<<gb(NN), 256>>>(p_h2lin, a_src2, a_dst2, p_als2, p_ald2);
        edge_exp_kernel<1><<<gb(ET), 256>>>(ei, p_als2, p_ald2, p_ex2, p_sum2);
        edge_agg_kernel<64, 64><<<gb(ET * 64), 256>>>(ei, p_h2lin, p_ex2, p_sum2, p_h2);
        bias_kernel<<<gb(NN * 64), 256>>>(p_h2, b2, NN * 64, 64);

        // ---- GRU layer 0 (gi factored through node-level P/Q) ----
        sgemm_kernel<true, false><<<ggrid(NN, 384), 256>>>(p_h2, Wih0, bih0, p_P,
                                                           NN, 64, 128, 384);
        sgemm_kernel<true, false><<<ggrid(NN, 384), 256>>>(p_h2, Wih0 + 64, nullptr, p_Q,
                                                           NN, 64, 128, 384);
        sgemm_kernel<true, false><<<ggrid(EE, 384), 256>>>(p_h0, Whh0, bhh0, p_gh,
                                                           EE, 128, 128, 384);
        gru_gate0_kernel<<<gb(EE * 128), 256>>>(ei, p_P, p_Q, p_gh, p_h0);

        // ---- GRU layer 1 ----
        sgemm_kernel<true, false><<<ggrid(EE, 384), 256>>>(p_h0, Wih1, bih1, p_gi,
                                                           EE, 128, 128, 384);
        sgemm_kernel<true, false><<<ggrid(EE, 384), 256>>>(p_h1s, Whh1, bhh1, p_gh,
                                                           EE, 128, 128, 384);
        gru_gate_kernel<<<gb(EE * 128), 256>>>(p_gi, p_gh, p_h1s);
    }

    // ---- decoder ----
    sgemm_kernel<false, true><<<ggrid(EE, 64), 256>>>(p_h1s, Wd1, bd1, p_dec1,
                                                      EE, 128, 64, 64);
    decoder2_kernel<<<gb(EE), 256>>>(p_dec1, Wd2, bd2, out);
}